// round 1
// baseline (speedup 1.0000x reference)
#include <cuda_runtime.h>
#include <math.h>
#include <stdint.h>

#define NN 50000
#define EE 800000
#define HH 4
#define DD 64
#define HDIM 256
#define NETT 8
#define CCC 16

// ---------------- scratch (static device globals; no allocs) ----------------
__device__ float g_h[NN * 64];
__device__ float g_feat[(size_t)NN * HDIM];
__device__ float g_out[(size_t)NN * HDIM];
__device__ float g_el[NN * HH];
__device__ float g_er[NN * HH];
__device__ float g_logits[(size_t)EE * HH];
__device__ float g_a[(size_t)EE * HH];
__device__ float g_ra[(size_t)EE * HH];
__device__ float g_es[NETT * HH];
__device__ float g_res2[NN * CCC];
__device__ int g_deg[NN];
__device__ int g_rowptr[NN + 1];
__device__ int g_fill[NN];
__device__ int g_eid[EE];

__device__ __forceinline__ float lrelu(float x) { return x > 0.f ? x : 0.2f * x; }

// ---------------- CSR build ----------------
__global__ void k_zero_int(int* p, int n) {
    int i = blockIdx.x * blockDim.x + threadIdx.x;
    if (i < n) p[i] = 0;
}

__global__ void k_hist(const int* __restrict__ dst) {
    int e = blockIdx.x * blockDim.x + threadIdx.x;
    if (e < EE) atomicAdd(&g_deg[dst[e]], 1);
}

__global__ void k_scan() {
    // single block, 1024 threads; exclusive scan of g_deg into g_rowptr/g_fill
    __shared__ int sums[1024];
    const int T = 1024;
    const int CH = (NN + T - 1) / T;
    int t = threadIdx.x;
    int start = t * CH;
    int lim = min(start + CH, NN);
    int s = 0;
    for (int i = start; i < lim; i++) s += g_deg[i];
    sums[t] = s;
    __syncthreads();
    for (int off = 1; off < T; off <<= 1) {
        int v = (t >= off) ? sums[t - off] : 0;
        __syncthreads();
        sums[t] += v;
        __syncthreads();
    }
    int run = (t == 0) ? 0 : sums[t - 1];
    for (int i = start; i < lim; i++) {
        g_rowptr[i] = run;
        g_fill[i] = run;
        run += g_deg[i];
    }
    if (t == T - 1) g_rowptr[NN] = run;
}

__global__ void k_scatter(const int* __restrict__ dst) {
    int e = blockIdx.x * blockDim.x + threadIdx.x;
    if (e < EE) {
        int p = atomicAdd(&g_fill[dst[e]], 1);
        g_eid[p] = e;
    }
}

// ---------------- tiled fp32 GEMM:  C[M,Nc] = A[M,K] * B[Nc,K]^T (+bias) ----------------
#define BM 64
#define BN 64
#define BK 32

__global__ void gemm_nt(const float* __restrict__ A, const float* __restrict__ B,
                        const float* __restrict__ bias, float* __restrict__ C,
                        int M, int Nc, int K) {
    __shared__ float As[BK][BM];
    __shared__ float Bs[BK][BN];
    int t = threadIdx.x;  // 256 threads
    int tx = t & 15, ty = t >> 4;
    int bm = blockIdx.x * BM, bn = blockIdx.y * BN;
    float acc[4][4] = {};
    for (int k0 = 0; k0 < K; k0 += BK) {
#pragma unroll
        for (int q = 0; q < 2; q++) {
            int f = t + q * 256;      // 0..511 float4 slots
            int row = f >> 3;         // 0..63
            int c4 = f & 7;           // 0..7
            int gr = bm + row;
            float4 v = make_float4(0.f, 0.f, 0.f, 0.f);
            if (gr < M) v = *reinterpret_cast<const float4*>(A + (size_t)gr * K + k0 + c4 * 4);
            As[c4 * 4 + 0][row] = v.x;
            As[c4 * 4 + 1][row] = v.y;
            As[c4 * 4 + 2][row] = v.z;
            As[c4 * 4 + 3][row] = v.w;
            int gc = bn + row;
            float4 w = make_float4(0.f, 0.f, 0.f, 0.f);
            if (gc < Nc) w = *reinterpret_cast<const float4*>(B + (size_t)gc * K + k0 + c4 * 4);
            Bs[c4 * 4 + 0][row] = w.x;
            Bs[c4 * 4 + 1][row] = w.y;
            Bs[c4 * 4 + 2][row] = w.z;
            Bs[c4 * 4 + 3][row] = w.w;
        }
        __syncthreads();
#pragma unroll
        for (int kk = 0; kk < BK; kk++) {
            float4 ra = *reinterpret_cast<const float4*>(&As[kk][ty * 4]);
            float4 rb = *reinterpret_cast<const float4*>(&Bs[kk][tx * 4]);
            float av[4] = {ra.x, ra.y, ra.z, ra.w};
            float bv[4] = {rb.x, rb.y, rb.z, rb.w};
#pragma unroll
            for (int i = 0; i < 4; i++)
#pragma unroll
                for (int j = 0; j < 4; j++) acc[i][j] += av[i] * bv[j];
        }
        __syncthreads();
    }
#pragma unroll
    for (int i = 0; i < 4; i++) {
        int gr = bm + ty * 4 + i;
        if (gr >= M) continue;
#pragma unroll
        for (int j = 0; j < 4; j++) {
            int gc = bn + tx * 4 + j;
            if (gc >= Nc) continue;
            float v = acc[i][j];
            if (bias) v += bias[gc];
            C[(size_t)gr * Nc + gc] = v;
        }
    }
}

// ---------------- edge-type attention term: es[t,h] = sum_d ae[h,d] * (etab[t] . We[h*ED+d]) ----------------
__global__ void k_es(const float* __restrict__ etab, const float* __restrict__ We,
                     const float* __restrict__ ae, float* __restrict__ es, int H) {
    int b = blockIdx.x;  // NETT*H blocks
    int t = b / H, h = b % H;
    int d = threadIdx.x;  // 64 threads
    const float* wr = We + (size_t)(h * 64 + d) * 64;
    const float* er = etab + t * 64;
    float dot = 0.f;
#pragma unroll
    for (int k = 0; k < 64; k++) dot += er[k] * wr[k];
    float v = ae[h * 64 + d] * dot;
    __shared__ float sm[64];
    sm[d] = v;
    __syncthreads();
    if (d < 32) {
        float x = sm[d] + sm[d + 32];
#pragma unroll
        for (int o = 16; o; o >>= 1) x += __shfl_xor_sync(0xffffffffu, x, o);
        if (d == 0) es[t * H + h] = x;
    }
}

// ---------------- per-node attention projections (H=4,D=64): warp per (n,h) ----------------
__global__ void k_elr(const float* __restrict__ feat, const float* __restrict__ al,
                      const float* __restrict__ ar, float* __restrict__ el,
                      float* __restrict__ er) {
    int w = (blockIdx.x * blockDim.x + threadIdx.x) >> 5;
    int lane = threadIdx.x & 31;
    if (w >= NN * HH) return;
    int n = w >> 2, h = w & 3;
    const float* f = feat + ((size_t)n * HH + h) * DD;
    float f1 = f[lane], f2 = f[lane + 32];
    float e1 = f1 * al[h * DD + lane] + f2 * al[h * DD + lane + 32];
    float e2 = f1 * ar[h * DD + lane] + f2 * ar[h * DD + lane + 32];
#pragma unroll
    for (int o = 16; o; o >>= 1) {
        e1 += __shfl_xor_sync(0xffffffffu, e1, o);
        e2 += __shfl_xor_sync(0xffffffffu, e2, o);
    }
    if (!lane) {
        el[n * HH + h] = e1;
        er[n * HH + h] = e2;
    }
}

// ---------------- per-edge logits (H=4) ----------------
__global__ void k_logits4(const int* __restrict__ src, const int* __restrict__ dst,
                          const int* __restrict__ et) {
    int e = blockIdx.x * blockDim.x + threadIdx.x;
    if (e >= EE) return;
    int s = src[e], d = dst[e], t = et[e];
    float4 a = *reinterpret_cast<const float4*>(&g_el[s * 4]);
    float4 b = *reinterpret_cast<const float4*>(&g_er[d * 4]);
    float4 c = *reinterpret_cast<const float4*>(&g_es[t * 4]);
    float4 r;
    r.x = lrelu(a.x + b.x + c.x);
    r.y = lrelu(a.y + b.y + c.y);
    r.z = lrelu(a.z + b.z + c.z);
    r.w = lrelu(a.w + b.w + c.w);
    *reinterpret_cast<float4*>(&g_logits[(size_t)e * 4]) = r;
}

// ---------------- per-dst softmax over CSR (H=4): warp per node ----------------
__global__ void k_softmax4(float* __restrict__ aout, const float* __restrict__ ramix) {
    int w = (blockIdx.x * blockDim.x + threadIdx.x) >> 5;
    int lane = threadIdx.x & 31;
    if (w >= NN) return;
    int st = g_rowptr[w], en = g_rowptr[w + 1];
    float4 mx = make_float4(-1e30f, -1e30f, -1e30f, -1e30f);
    for (int k = st + lane; k < en; k += 32) {
        float4 lg = *reinterpret_cast<const float4*>(&g_logits[(size_t)g_eid[k] * 4]);
        mx.x = fmaxf(mx.x, lg.x);
        mx.y = fmaxf(mx.y, lg.y);
        mx.z = fmaxf(mx.z, lg.z);
        mx.w = fmaxf(mx.w, lg.w);
    }
#pragma unroll
    for (int o = 16; o; o >>= 1) {
        mx.x = fmaxf(mx.x, __shfl_xor_sync(0xffffffffu, mx.x, o));
        mx.y = fmaxf(mx.y, __shfl_xor_sync(0xffffffffu, mx.y, o));
        mx.z = fmaxf(mx.z, __shfl_xor_sync(0xffffffffu, mx.z, o));
        mx.w = fmaxf(mx.w, __shfl_xor_sync(0xffffffffu, mx.w, o));
    }
    float4 sum = make_float4(0.f, 0.f, 0.f, 0.f);
    for (int k = st + lane; k < en; k += 32) {
        float4 lg = *reinterpret_cast<const float4*>(&g_logits[(size_t)g_eid[k] * 4]);
        sum.x += expf(lg.x - mx.x);
        sum.y += expf(lg.y - mx.y);
        sum.z += expf(lg.z - mx.z);
        sum.w += expf(lg.w - mx.w);
    }
#pragma unroll
    for (int o = 16; o; o >>= 1) {
        sum.x += __shfl_xor_sync(0xffffffffu, sum.x, o);
        sum.y += __shfl_xor_sync(0xffffffffu, sum.y, o);
        sum.z += __shfl_xor_sync(0xffffffffu, sum.z, o);
        sum.w += __shfl_xor_sync(0xffffffffu, sum.w, o);
    }
    float4 inv;
    inv.x = 1.f / (sum.x + 1e-9f);
    inv.y = 1.f / (sum.y + 1e-9f);
    inv.z = 1.f / (sum.z + 1e-9f);
    inv.w = 1.f / (sum.w + 1e-9f);
    for (int k = st + lane; k < en; k += 32) {
        int e = g_eid[k];
        float4 lg = *reinterpret_cast<const float4*>(&g_logits[(size_t)e * 4]);
        float4 av;
        av.x = expf(lg.x - mx.x) * inv.x;
        av.y = expf(lg.y - mx.y) * inv.y;
        av.z = expf(lg.z - mx.z) * inv.z;
        av.w = expf(lg.w - mx.w) * inv.w;
        if (ramix) {
            float4 r = *reinterpret_cast<const float4*>(&ramix[(size_t)e * 4]);
            av.x = av.x * 0.95f + 0.05f * r.x;
            av.y = av.y * 0.95f + 0.05f * r.y;
            av.z = av.z * 0.95f + 0.05f * r.z;
            av.w = av.w * 0.95f + 0.05f * r.w;
        }
        *reinterpret_cast<float4*>(&aout[(size_t)e * 4]) = av;
    }
}

// ---------------- aggregation over CSR (H=4, 256 feats): block per node ----------------
__global__ void k_agg4(const int* __restrict__ src, const float* __restrict__ a,
                       const float* __restrict__ feat, const float* __restrict__ res,
                       float* __restrict__ out, int act) {
    int n = blockIdx.x;
    int t = threadIdx.x;  // 256
    int h = t >> 6;
    int st = g_rowptr[n], en = g_rowptr[n + 1];
    float acc = 0.f;
    for (int k = st; k < en; k++) {
        int e = g_eid[k];
        int s = src[e];
        acc += __ldg(&a[(size_t)e * 4 + h]) * __ldg(&feat[(size_t)s * 256 + t]);
    }
    if (res) acc += res[(size_t)n * 256 + t];
    if (act) acc = acc > 0.f ? acc : expf(acc) - 1.f;
    out[(size_t)n * 256 + t] = acc;
}

// ---------------- layer 2 (H=1, C=16) ----------------
__global__ void k_elr2(const float* __restrict__ feat2, const float* __restrict__ al2,
                       const float* __restrict__ ar2, float* __restrict__ el,
                       float* __restrict__ er) {
    int n = blockIdx.x * blockDim.x + threadIdx.x;
    if (n >= NN) return;
    float e1 = 0.f, e2 = 0.f;
#pragma unroll
    for (int c = 0; c < 16; c++) {
        float f = feat2[(size_t)n * 16 + c];
        e1 += f * al2[c];
        e2 += f * ar2[c];
    }
    el[n] = e1;
    er[n] = e2;
}

__global__ void k_logits1(const int* __restrict__ src, const int* __restrict__ dst,
                          const int* __restrict__ et) {
    int e = blockIdx.x * blockDim.x + threadIdx.x;
    if (e >= EE) return;
    g_logits[e] = lrelu(g_el[src[e]] + g_er[dst[e]] + g_es[et[e]]);
}

__global__ void k_softmax1(float* __restrict__ aout) {
    int w = (blockIdx.x * blockDim.x + threadIdx.x) >> 5;
    int lane = threadIdx.x & 31;
    if (w >= NN) return;
    int st = g_rowptr[w], en = g_rowptr[w + 1];
    float mx = -1e30f;
    for (int k = st + lane; k < en; k += 32) mx = fmaxf(mx, g_logits[g_eid[k]]);
#pragma unroll
    for (int o = 16; o; o >>= 1) mx = fmaxf(mx, __shfl_xor_sync(0xffffffffu, mx, o));
    float sum = 0.f;
    for (int k = st + lane; k < en; k += 32) sum += expf(g_logits[g_eid[k]] - mx);
#pragma unroll
    for (int o = 16; o; o >>= 1) sum += __shfl_xor_sync(0xffffffffu, sum, o);
    float inv = 1.f / (sum + 1e-9f);
    for (int k = st + lane; k < en; k += 32) {
        int e = g_eid[k];
        aout[e] = expf(g_logits[e] - mx) * inv;
    }
}

__global__ void k_agg2(const int* __restrict__ src, const float* __restrict__ a,
                       const float* __restrict__ feat2, const float* __restrict__ res2,
                       float* __restrict__ out) {
    int i = blockIdx.x * blockDim.x + threadIdx.x;
    if (i >= NN * 16) return;
    int n = i >> 4, c = i & 15;
    int st = g_rowptr[n], en = g_rowptr[n + 1];
    float acc = 0.f;
    for (int k = st; k < en; k++) {
        int e = g_eid[k];
        acc += a[e] * feat2[(size_t)src[e] * 16 + c];
    }
    acc += res2[(size_t)n * 16 + c];
    out[i] = acc;
}

// ---------------- host orchestration ----------------
static inline int cdiv(int a, int b) { return (a + b - 1) / b; }

extern "C" void kernel_launch(void* const* d_in, const int* in_sizes, int n_in,
                              void* d_out, int out_size) {
    (void)in_sizes;
    (void)n_in;
    (void)out_size;
    const float* x0 = (const float*)d_in[0];
    const float* x1 = (const float*)d_in[1];
    const float* x2 = (const float*)d_in[2];
    const int* src = (const int*)d_in[3];
    const int* dst = (const int*)d_in[4];
    const int* efeat = (const int*)d_in[5];
    const float* W0 = (const float*)d_in[6];
    const float* b0 = (const float*)d_in[7];
    const float* W1 = (const float*)d_in[8];
    const float* b1 = (const float*)d_in[9];
    const float* W2 = (const float*)d_in[10];
    const float* b2 = (const float*)d_in[11];
    const float* Wg0 = (const float*)d_in[12];
    const float* etab0 = (const float*)d_in[13];
    const float* We0 = (const float*)d_in[14];
    const float* al0 = (const float*)d_in[15];
    const float* ar0 = (const float*)d_in[16];
    const float* ae0 = (const float*)d_in[17];
    const float* Wg1 = (const float*)d_in[18];
    const float* etab1 = (const float*)d_in[19];
    const float* We1 = (const float*)d_in[20];
    const float* al1 = (const float*)d_in[21];
    const float* ar1 = (const float*)d_in[22];
    const float* ae1 = (const float*)d_in[23];
    const float* Wg2 = (const float*)d_in[24];
    const float* etab2 = (const float*)d_in[25];
    const float* We2 = (const float*)d_in[26];
    const float* al2 = (const float*)d_in[27];
    const float* ar2 = (const float*)d_in[28];
    const float* ae2 = (const float*)d_in[29];
    const float* resW2 = (const float*)d_in[30];
    float* out = (float*)d_out;

    // device-global scratch addresses
    void* p;
    cudaGetSymbolAddress(&p, g_h);       float* dh = (float*)p;
    cudaGetSymbolAddress(&p, g_feat);    float* dfeat = (float*)p;
    cudaGetSymbolAddress(&p, g_out);     float* dout_l = (float*)p;
    cudaGetSymbolAddress(&p, g_el);      float* del = (float*)p;
    cudaGetSymbolAddress(&p, g_er);      float* der = (float*)p;
    cudaGetSymbolAddress(&p, g_a);       float* da = (float*)p;
    cudaGetSymbolAddress(&p, g_ra);      float* dra = (float*)p;
    cudaGetSymbolAddress(&p, g_es);      float* des = (float*)p;
    cudaGetSymbolAddress(&p, g_res2);    float* dres2 = (float*)p;
    cudaGetSymbolAddress(&p, g_deg);     int* ddeg = (int*)p;

    // ---- CSR build ----
    k_zero_int<<<cdiv(NN, 256), 256>>>(ddeg, NN);
    k_hist<<<cdiv(EE, 256), 256>>>(dst);
    k_scan<<<1, 1024>>>();
    k_scatter<<<cdiv(EE, 256), 256>>>(dst);

    // ---- input projections -> h [N,64] ----
    {
        dim3 g0(cdiv(20000, BM), cdiv(64, BN));
        gemm_nt<<<g0, 256>>>(x0, W0, b0, dh, 20000, 64, 128);
        dim3 g1(cdiv(15000, BM), cdiv(64, BN));
        gemm_nt<<<g1, 256>>>(x1, W1, b1, dh + (size_t)20000 * 64, 15000, 64, 64);
        gemm_nt<<<g1, 256>>>(x2, W2, b2, dh + (size_t)35000 * 64, 15000, 64, 32);
    }

    // ---- GAT layer 0 ----
    {
        dim3 gg(cdiv(NN, BM), cdiv(HDIM, BN));
        gemm_nt<<<gg, 256>>>(dh, Wg0, nullptr, dfeat, NN, HDIM, 64);
        k_es<<<NETT * HH, 64>>>(etab0, We0, ae0, des, HH);
        k_elr<<<cdiv(NN * HH * 32, 256), 256>>>(dfeat, al0, ar0, del, der);
        k_logits4<<<cdiv(EE, 256), 256>>>(src, dst, efeat);
        k_softmax4<<<cdiv(NN * 32, 256), 256>>>(dra, nullptr);  // a0 -> g_ra
        k_agg4<<<NN, 256>>>(src, dra, dfeat, nullptr, dout_l, 1);  // elu, no residual
    }

    // ---- GAT layer 1 ----
    {
        dim3 gg(cdiv(NN, BM), cdiv(HDIM, BN));
        gemm_nt<<<gg, 256>>>(dout_l, Wg1, nullptr, dfeat, NN, HDIM, HDIM);
        k_es<<<NETT * HH, 64>>>(etab1, We1, ae1, des, HH);
        k_elr<<<cdiv(NN * HH * 32, 256), 256>>>(dfeat, al1, ar1, del, der);
        k_logits4<<<cdiv(EE, 256), 256>>>(src, dst, efeat);
        k_softmax4<<<cdiv(NN * 32, 256), 256>>>(da, dra);  // mix with ra
        k_agg4<<<NN, 256>>>(src, da, dfeat, dout_l, dout_l, 1);  // identity residual + elu (in-place safe)
    }

    // ---- GAT layer 2 (H=1, C=16) ----
    {
        dim3 gg(cdiv(NN, BM), cdiv(CCC, BN));
        gemm_nt<<<gg, 256>>>(dout_l, Wg2, nullptr, dfeat, NN, CCC, HDIM);    // feat2 (reuse g_feat)
        gemm_nt<<<gg, 256>>>(dout_l, resW2, nullptr, dres2, NN, CCC, HDIM);  // residual proj
        k_es<<<NETT * 1, 64>>>(etab2, We2, ae2, des, 1);
        k_elr2<<<cdiv(NN, 256), 256>>>(dfeat, al2, ar2, del, der);
        k_logits1<<<cdiv(EE, 256), 256>>>(src, dst, efeat);
        k_softmax1<<<cdiv(NN * 32, 256), 256>>>(da);
        k_agg2<<<cdiv(NN * 16, 256), 256>>>(src, da, dfeat, dres2, out);
    }
}

// round 3
// speedup vs baseline: 1.3393x; 1.3393x over previous
#include <cuda_runtime.h>
#include <math.h>
#include <stdint.h>

#define NN 50000
#define EE 800000
#define HH 4
#define DD 64
#define HDIM 256
#define NETT 8
#define CCC 16

// ---------------- scratch (static device globals; no allocs) ----------------
__device__ float g_h[NN * 64];
__device__ float g_feat[(size_t)NN * HDIM];
__device__ float g_out[(size_t)NN * HDIM];
__device__ float g_el[NN * HH];
__device__ float g_er[NN * HH];
__device__ float g_logits[(size_t)EE * HH];   // CSR order
__device__ float g_a[(size_t)EE * HH];        // CSR order
__device__ float g_ra[(size_t)EE * HH];       // CSR order (layer0 attention)
__device__ float g_es[NETT * HH];
__device__ float g_B2[32 * HDIM];             // concat Wg2 | resW2
__device__ int g_deg[NN];
__device__ int g_rowptr[NN + 1];
__device__ int g_fill[NN];
__device__ int g_src_csr[EE];
__device__ int g_et_csr[EE];

__device__ __forceinline__ float lrelu(float x) { return x > 0.f ? x : 0.2f * x; }

// ---------------- CSR build ----------------
__global__ void k_zero_int(int* p, int n) {
    int i = blockIdx.x * blockDim.x + threadIdx.x;
    if (i < n) p[i] = 0;
}

__global__ void k_hist(const int* __restrict__ dst) {
    int e = blockIdx.x * blockDim.x + threadIdx.x;
    if (e < EE) atomicAdd(&g_deg[dst[e]], 1);
}

__global__ void k_scan() {
    __shared__ int sums[1024];
    const int T = 1024;
    const int CH = (NN + T - 1) / T;
    int t = threadIdx.x;
    int start = t * CH;
    int lim = min(start + CH, NN);
    int s = 0;
    for (int i = start; i < lim; i++) s += g_deg[i];
    sums[t] = s;
    __syncthreads();
    for (int off = 1; off < T; off <<= 1) {
        int v = (t >= off) ? sums[t - off] : 0;
        __syncthreads();
        sums[t] += v;
        __syncthreads();
    }
    int run = (t == 0) ? 0 : sums[t - 1];
    for (int i = start; i < lim; i++) {
        g_rowptr[i] = run;
        g_fill[i] = run;
        run += g_deg[i];
    }
    if (t == T - 1) g_rowptr[NN] = run;
}

__global__ void k_scatter(const int* __restrict__ src, const int* __restrict__ dst,
                          const int* __restrict__ et) {
    int e = blockIdx.x * blockDim.x + threadIdx.x;
    if (e < EE) {
        int p = atomicAdd(&g_fill[dst[e]], 1);
        g_src_csr[p] = src[e];
        g_et_csr[p] = et[e];
    }
}

// ---------------- generic tiled fp32 GEMM (64x64x32): C[M,Nc] = A[M,K] B[Nc,K]^T (+bias) ----------------
#define BM 64
#define BN 64
#define BK 32

__global__ void gemm_nt(const float* __restrict__ A, const float* __restrict__ B,
                        const float* __restrict__ bias, float* __restrict__ C,
                        int M, int Nc, int K) {
    __shared__ float As[BK][BM];
    __shared__ float Bs[BK][BN];
    int t = threadIdx.x;
    int tx = t & 15, ty = t >> 4;
    int bm = blockIdx.x * BM, bn = blockIdx.y * BN;
    float acc[4][4] = {};
    for (int k0 = 0; k0 < K; k0 += BK) {
#pragma unroll
        for (int q = 0; q < 2; q++) {
            int f = t + q * 256;
            int row = f >> 3;
            int c4 = f & 7;
            int gr = bm + row;
            float4 v = make_float4(0.f, 0.f, 0.f, 0.f);
            if (gr < M) v = *reinterpret_cast<const float4*>(A + (size_t)gr * K + k0 + c4 * 4);
            As[c4 * 4 + 0][row] = v.x;
            As[c4 * 4 + 1][row] = v.y;
            As[c4 * 4 + 2][row] = v.z;
            As[c4 * 4 + 3][row] = v.w;
            int gc = bn + row;
            float4 w = make_float4(0.f, 0.f, 0.f, 0.f);
            if (gc < Nc) w = *reinterpret_cast<const float4*>(B + (size_t)gc * K + k0 + c4 * 4);
            Bs[c4 * 4 + 0][row] = w.x;
            Bs[c4 * 4 + 1][row] = w.y;
            Bs[c4 * 4 + 2][row] = w.z;
            Bs[c4 * 4 + 3][row] = w.w;
        }
        __syncthreads();
#pragma unroll
        for (int kk = 0; kk < BK; kk++) {
            float4 ra = *reinterpret_cast<const float4*>(&As[kk][ty * 4]);
            float4 rb = *reinterpret_cast<const float4*>(&Bs[kk][tx * 4]);
            float av[4] = {ra.x, ra.y, ra.z, ra.w};
            float bv[4] = {rb.x, rb.y, rb.z, rb.w};
#pragma unroll
            for (int i = 0; i < 4; i++)
#pragma unroll
                for (int j = 0; j < 4; j++) acc[i][j] += av[i] * bv[j];
        }
        __syncthreads();
    }
#pragma unroll
    for (int i = 0; i < 4; i++) {
        int gr = bm + ty * 4 + i;
        if (gr >= M) continue;
#pragma unroll
        for (int j = 0; j < 4; j++) {
            int gc = bn + tx * 4 + j;
            if (gc >= Nc) continue;
            float v = acc[i][j];
            if (bias) v += bias[gc];
            C[(size_t)gr * Nc + gc] = v;
        }
    }
}

// ---------------- big GEMM (128x128x16, double-buffered, 8x8/thread) ----------------
#define GBM 128
#define GBN 128
#define GBK 16

__global__ __launch_bounds__(256, 2) void gemm128(const float* __restrict__ A,
                                                  const float* __restrict__ B,
                                                  float* __restrict__ C,
                                                  int M, int Nc, int K) {
    __shared__ float As[2][GBK][GBM];
    __shared__ float Bs[2][GBK][GBN];
    int t = threadIdx.x;
    int tx = t & 15, ty = t >> 4;
    int bm = blockIdx.x * GBM, bn = blockIdx.y * GBN;
    // load-slot mapping: thread handles rows (t>>2) and (t>>2)+64, c4 = t&3
    int lrow = t >> 2;
    int lc4 = t & 3;

    float4 pa[2], pb[2];
    auto ldg = [&](int k0) {
#pragma unroll
        for (int q = 0; q < 2; q++) {
            int row = lrow + q * 64;
            int gr = bm + row;
            pa[q] = make_float4(0.f, 0.f, 0.f, 0.f);
            if (gr < M) pa[q] = *reinterpret_cast<const float4*>(A + (size_t)gr * K + k0 + lc4 * 4);
            int gc = bn + row;
            pb[q] = make_float4(0.f, 0.f, 0.f, 0.f);
            if (gc < Nc) pb[q] = *reinterpret_cast<const float4*>(B + (size_t)gc * K + k0 + lc4 * 4);
        }
    };
    auto sts = [&](int buf) {
#pragma unroll
        for (int q = 0; q < 2; q++) {
            int row = lrow + q * 64;
            As[buf][lc4 * 4 + 0][row] = pa[q].x;
            As[buf][lc4 * 4 + 1][row] = pa[q].y;
            As[buf][lc4 * 4 + 2][row] = pa[q].z;
            As[buf][lc4 * 4 + 3][row] = pa[q].w;
            Bs[buf][lc4 * 4 + 0][row] = pb[q].x;
            Bs[buf][lc4 * 4 + 1][row] = pb[q].y;
            Bs[buf][lc4 * 4 + 2][row] = pb[q].z;
            Bs[buf][lc4 * 4 + 3][row] = pb[q].w;
        }
    };

    float acc[8][8] = {};
    int nt = K / GBK;
    ldg(0);
    sts(0);
    __syncthreads();
    for (int it = 0; it < nt; it++) {
        int cur = it & 1;
        bool has = (it + 1) < nt;
        if (has) ldg((it + 1) * GBK);
#pragma unroll
        for (int kk = 0; kk < GBK; kk++) {
            float4 a0 = *reinterpret_cast<const float4*>(&As[cur][kk][ty * 4]);
            float4 a1 = *reinterpret_cast<const float4*>(&As[cur][kk][ty * 4 + 64]);
            float4 b0 = *reinterpret_cast<const float4*>(&Bs[cur][kk][tx * 4]);
            float4 b1 = *reinterpret_cast<const float4*>(&Bs[cur][kk][tx * 4 + 64]);
            float av[8] = {a0.x, a0.y, a0.z, a0.w, a1.x, a1.y, a1.z, a1.w};
            float bv[8] = {b0.x, b0.y, b0.z, b0.w, b1.x, b1.y, b1.z, b1.w};
#pragma unroll
            for (int i = 0; i < 8; i++)
#pragma unroll
                for (int j = 0; j < 8; j++) acc[i][j] += av[i] * bv[j];
        }
        if (has) sts(cur ^ 1);
        __syncthreads();
    }
#pragma unroll
    for (int hi = 0; hi < 2; hi++) {
#pragma unroll
        for (int i = 0; i < 4; i++) {
            int gr = bm + ty * 4 + hi * 64 + i;
            if (gr >= M) continue;
#pragma unroll
            for (int hj = 0; hj < 2; hj++) {
                int gc = bn + tx * 4 + hj * 64;
                if (gc + 3 >= Nc) continue;
                float4 v;
                v.x = acc[hi * 4 + i][hj * 4 + 0];
                v.y = acc[hi * 4 + i][hj * 4 + 1];
                v.z = acc[hi * 4 + i][hj * 4 + 2];
                v.w = acc[hi * 4 + i][hj * 4 + 3];
                *reinterpret_cast<float4*>(C + (size_t)gr * Nc + gc) = v;
            }
        }
    }
}

// ---------------- edge-type attention term ----------------
__global__ void k_es(const float* __restrict__ etab, const float* __restrict__ We,
                     const float* __restrict__ ae, float* __restrict__ es, int H) {
    int b = blockIdx.x;
    int t = b / H, h = b % H;
    int d = threadIdx.x;
    const float* wr = We + (size_t)(h * 64 + d) * 64;
    const float* er = etab + t * 64;
    float dot = 0.f;
#pragma unroll
    for (int k = 0; k < 64; k++) dot += er[k] * wr[k];
    float v = ae[h * 64 + d] * dot;
    __shared__ float sm[64];
    sm[d] = v;
    __syncthreads();
    if (d < 32) {
        float x = sm[d] + sm[d + 32];
#pragma unroll
        for (int o = 16; o; o >>= 1) x += __shfl_xor_sync(0xffffffffu, x, o);
        if (d == 0) es[t * H + h] = x;
    }
}

// ---------------- per-node attention projections ----------------
__global__ void k_elr(const float* __restrict__ feat, const float* __restrict__ al,
                      const float* __restrict__ ar, float* __restrict__ el,
                      float* __restrict__ er) {
    int w = (blockIdx.x * blockDim.x + threadIdx.x) >> 5;
    int lane = threadIdx.x & 31;
    if (w >= NN * HH) return;
    int n = w >> 2, h = w & 3;
    const float* f = feat + ((size_t)n * HH + h) * DD;
    float f1 = f[lane], f2 = f[lane + 32];
    float e1 = f1 * al[h * DD + lane] + f2 * al[h * DD + lane + 32];
    float e2 = f1 * ar[h * DD + lane] + f2 * ar[h * DD + lane + 32];
#pragma unroll
    for (int o = 16; o; o >>= 1) {
        e1 += __shfl_xor_sync(0xffffffffu, e1, o);
        e2 += __shfl_xor_sync(0xffffffffu, e2, o);
    }
    if (!lane) {
        el[n * HH + h] = e1;
        er[n * HH + h] = e2;
    }
}

// ---------------- fused logits + softmax (H=4), CSR order, warp per node ----------------
__global__ void k_attn4(const float* __restrict__ el, const float* __restrict__ er,
                        const float* __restrict__ es, float* __restrict__ aout,
                        const float* __restrict__ ramix) {
    int w = (blockIdx.x * blockDim.x + threadIdx.x) >> 5;
    int lane = threadIdx.x & 31;
    if (w >= NN) return;
    int st = g_rowptr[w], en = g_rowptr[w + 1];
    float4 ern = *reinterpret_cast<const float4*>(&er[w * 4]);
    float4 mx = make_float4(-1e30f, -1e30f, -1e30f, -1e30f);
    for (int k = st + lane; k < en; k += 32) {
        int s = g_src_csr[k], t = g_et_csr[k];
        float4 a = *reinterpret_cast<const float4*>(&el[s * 4]);
        float4 c = *reinterpret_cast<const float4*>(&es[t * 4]);
        float4 lg;
        lg.x = lrelu(a.x + ern.x + c.x);
        lg.y = lrelu(a.y + ern.y + c.y);
        lg.z = lrelu(a.z + ern.z + c.z);
        lg.w = lrelu(a.w + ern.w + c.w);
        *reinterpret_cast<float4*>(&g_logits[(size_t)k * 4]) = lg;
        mx.x = fmaxf(mx.x, lg.x);
        mx.y = fmaxf(mx.y, lg.y);
        mx.z = fmaxf(mx.z, lg.z);
        mx.w = fmaxf(mx.w, lg.w);
    }
#pragma unroll
    for (int o = 16; o; o >>= 1) {
        mx.x = fmaxf(mx.x, __shfl_xor_sync(0xffffffffu, mx.x, o));
        mx.y = fmaxf(mx.y, __shfl_xor_sync(0xffffffffu, mx.y, o));
        mx.z = fmaxf(mx.z, __shfl_xor_sync(0xffffffffu, mx.z, o));
        mx.w = fmaxf(mx.w, __shfl_xor_sync(0xffffffffu, mx.w, o));
    }
    float4 sum = make_float4(0.f, 0.f, 0.f, 0.f);
    for (int k = st + lane; k < en; k += 32) {
        float4 lg = *reinterpret_cast<const float4*>(&g_logits[(size_t)k * 4]);
        sum.x += expf(lg.x - mx.x);
        sum.y += expf(lg.y - mx.y);
        sum.z += expf(lg.z - mx.z);
        sum.w += expf(lg.w - mx.w);
    }
#pragma unroll
    for (int o = 16; o; o >>= 1) {
        sum.x += __shfl_xor_sync(0xffffffffu, sum.x, o);
        sum.y += __shfl_xor_sync(0xffffffffu, sum.y, o);
        sum.z += __shfl_xor_sync(0xffffffffu, sum.z, o);
        sum.w += __shfl_xor_sync(0xffffffffu, sum.w, o);
    }
    float4 inv;
    inv.x = 1.f / (sum.x + 1e-9f);
    inv.y = 1.f / (sum.y + 1e-9f);
    inv.z = 1.f / (sum.z + 1e-9f);
    inv.w = 1.f / (sum.w + 1e-9f);
    for (int k = st + lane; k < en; k += 32) {
        float4 lg = *reinterpret_cast<const float4*>(&g_logits[(size_t)k * 4]);
        float4 av;
        av.x = expf(lg.x - mx.x) * inv.x;
        av.y = expf(lg.y - mx.y) * inv.y;
        av.z = expf(lg.z - mx.z) * inv.z;
        av.w = expf(lg.w - mx.w) * inv.w;
        if (ramix) {
            float4 r = *reinterpret_cast<const float4*>(&ramix[(size_t)k * 4]);
            av.x = av.x * 0.95f + 0.05f * r.x;
            av.y = av.y * 0.95f + 0.05f * r.y;
            av.z = av.z * 0.95f + 0.05f * r.z;
            av.w = av.w * 0.95f + 0.05f * r.w;
        }
        *reinterpret_cast<float4*>(&aout[(size_t)k * 4]) = av;
    }
}

// ---------------- aggregation (H=4, 256 feats), CSR order, block per node ----------------
__global__ void k_agg4(const float* __restrict__ a, const float* __restrict__ feat,
                       const float* __restrict__ res, float* __restrict__ out, int act) {
    int n = blockIdx.x;
    int t = threadIdx.x;
    int h = t >> 6;
    int st = g_rowptr[n], en = g_rowptr[n + 1];
    float acc0 = 0.f, acc1 = 0.f;
    int k = st;
    for (; k + 1 < en; k += 2) {
        int s0 = g_src_csr[k], s1 = g_src_csr[k + 1];
        float a0 = __ldg(&a[(size_t)k * 4 + h]);
        float a1 = __ldg(&a[(size_t)(k + 1) * 4 + h]);
        float f0 = __ldg(&feat[(size_t)s0 * 256 + t]);
        float f1 = __ldg(&feat[(size_t)s1 * 256 + t]);
        acc0 += a0 * f0;
        acc1 += a1 * f1;
    }
    if (k < en) {
        int s0 = g_src_csr[k];
        acc0 += __ldg(&a[(size_t)k * 4 + h]) * __ldg(&feat[(size_t)s0 * 256 + t]);
    }
    float acc = acc0 + acc1;
    if (res) acc += res[(size_t)n * 256 + t];
    if (act) acc = acc > 0.f ? acc : expf(acc) - 1.f;
    out[(size_t)n * 256 + t] = acc;
}

// ---------------- layer 2 (H=1, C=16; feat2/res2 interleaved stride 32) ----------------
__global__ void k_copyB2(const float* __restrict__ Wg2, const float* __restrict__ resW2) {
    int i = blockIdx.x * blockDim.x + threadIdx.x;
    if (i < 16 * 256) g_B2[i] = Wg2[i];
    else if (i < 32 * 256) g_B2[i] = resW2[i - 16 * 256];
}

__global__ void k_elr2(const float* __restrict__ fr, const float* __restrict__ al2,
                       const float* __restrict__ ar2, float* __restrict__ el,
                       float* __restrict__ er) {
    int n = blockIdx.x * blockDim.x + threadIdx.x;
    if (n >= NN) return;
    float e1 = 0.f, e2 = 0.f;
#pragma unroll
    for (int c = 0; c < 16; c++) {
        float f = fr[(size_t)n * 32 + c];
        e1 += f * al2[c];
        e2 += f * ar2[c];
    }
    el[n] = e1;
    er[n] = e2;
}

__global__ void k_attn1(const float* __restrict__ el, const float* __restrict__ er,
                        const float* __restrict__ es, float* __restrict__ aout) {
    int w = (blockIdx.x * blockDim.x + threadIdx.x) >> 5;
    int lane = threadIdx.x & 31;
    if (w >= NN) return;
    int st = g_rowptr[w], en = g_rowptr[w + 1];
    float ern = er[w];
    float mx = -1e30f;
    for (int k = st + lane; k < en; k += 32) {
        int s = g_src_csr[k], t = g_et_csr[k];
        float lg = lrelu(el[s] + ern + es[t]);
        g_logits[k] = lg;
        mx = fmaxf(mx, lg);
    }
#pragma unroll
    for (int o = 16; o; o >>= 1) mx = fmaxf(mx, __shfl_xor_sync(0xffffffffu, mx, o));
    float sum = 0.f;
    for (int k = st + lane; k < en; k += 32) sum += expf(g_logits[k] - mx);
#pragma unroll
    for (int o = 16; o; o >>= 1) sum += __shfl_xor_sync(0xffffffffu, sum, o);
    float inv = 1.f / (sum + 1e-9f);
    for (int k = st + lane; k < en; k += 32) aout[k] = expf(g_logits[k] - mx) * inv;
}

__global__ void k_agg2(const float* __restrict__ a, const float* __restrict__ fr,
                       float* __restrict__ out) {
    int i = blockIdx.x * blockDim.x + threadIdx.x;
    if (i >= NN * 16) return;
    int n = i >> 4, c = i & 15;
    int st = g_rowptr[n], en = g_rowptr[n + 1];
    float acc0 = 0.f, acc1 = 0.f;
    int k = st;
    for (; k + 1 < en; k += 2) {
        acc0 += __ldg(&a[k]) * __ldg(&fr[(size_t)g_src_csr[k] * 32 + c]);
        acc1 += __ldg(&a[k + 1]) * __ldg(&fr[(size_t)g_src_csr[k + 1] * 32 + c]);
    }
    if (k < en) acc0 += __ldg(&a[k]) * __ldg(&fr[(size_t)g_src_csr[k] * 32 + c]);
    out[i] = acc0 + acc1 + fr[(size_t)n * 32 + 16 + c];
}

// ---------------- host orchestration ----------------
static inline int cdiv(int a, int b) { return (a + b - 1) / b; }

extern "C" void kernel_launch(void* const* d_in, const int* in_sizes, int n_in,
                              void* d_out, int out_size) {
    (void)in_sizes;
    (void)n_in;
    (void)out_size;
    const float* x0 = (const float*)d_in[0];
    const float* x1 = (const float*)d_in[1];
    const float* x2 = (const float*)d_in[2];
    const int* src = (const int*)d_in[3];
    const int* dst = (const int*)d_in[4];
    const int* efeat = (const int*)d_in[5];
    const float* W0 = (const float*)d_in[6];
    const float* b0 = (const float*)d_in[7];
    const float* W1 = (const float*)d_in[8];
    const float* b1 = (const float*)d_in[9];
    const float* W2 = (const float*)d_in[10];
    const float* b2 = (const float*)d_in[11];
    const float* Wg0 = (const float*)d_in[12];
    const float* etab0 = (const float*)d_in[13];
    const float* We0 = (const float*)d_in[14];
    const float* al0 = (const float*)d_in[15];
    const float* ar0 = (const float*)d_in[16];
    const float* ae0 = (const float*)d_in[17];
    const float* Wg1 = (const float*)d_in[18];
    const float* etab1 = (const float*)d_in[19];
    const float* We1 = (const float*)d_in[20];
    const float* al1 = (const float*)d_in[21];
    const float* ar1 = (const float*)d_in[22];
    const float* ae1 = (const float*)d_in[23];
    const float* Wg2 = (const float*)d_in[24];
    const float* etab2 = (const float*)d_in[25];
    const float* We2 = (const float*)d_in[26];
    const float* al2 = (const float*)d_in[27];
    const float* ar2 = (const float*)d_in[28];
    const float* ae2 = (const float*)d_in[29];
    const float* resW2 = (const float*)d_in[30];
    float* out = (float*)d_out;

    void* p;
    cudaGetSymbolAddress(&p, g_h);      float* dh = (float*)p;
    cudaGetSymbolAddress(&p, g_feat);   float* dfeat = (float*)p;
    cudaGetSymbolAddress(&p, g_out);    float* dout_l = (float*)p;
    cudaGetSymbolAddress(&p, g_el);     float* del = (float*)p;
    cudaGetSymbolAddress(&p, g_er);     float* der = (float*)p;
    cudaGetSymbolAddress(&p, g_a);      float* da = (float*)p;
    cudaGetSymbolAddress(&p, g_ra);     float* dra = (float*)p;
    cudaGetSymbolAddress(&p, g_es);     float* des = (float*)p;
    cudaGetSymbolAddress(&p, g_B2);     float* dB2 = (float*)p;
    cudaGetSymbolAddress(&p, g_deg);    int* ddeg = (int*)p;

    // ---- CSR build ----
    k_zero_int<<<cdiv(NN, 256), 256>>>(ddeg, NN);
    k_hist<<<cdiv(EE, 256), 256>>>(dst);
    k_scan<<<1, 1024>>>();
    k_scatter<<<cdiv(EE, 256), 256>>>(src, dst, efeat);

    // ---- input projections -> h [N,64] ----
    {
        dim3 g0(cdiv(20000, BM), 1);
        gemm_nt<<<g0, 256>>>(x0, W0, b0, dh, 20000, 64, 128);
        dim3 g1(cdiv(15000, BM), 1);
        gemm_nt<<<g1, 256>>>(x1, W1, b1, dh + (size_t)20000 * 64, 15000, 64, 64);
        gemm_nt<<<g1, 256>>>(x2, W2, b2, dh + (size_t)35000 * 64, 15000, 64, 32);
    }

    // ---- GAT layer 0 ----
    {
        dim3 gg(cdiv(NN, GBM), cdiv(HDIM, GBN));
        gemm128<<<gg, 256>>>(dh, Wg0, dfeat, NN, HDIM, 64);
        k_es<<<NETT * HH, 64>>>(etab0, We0, ae0, des, HH);
        k_elr<<<cdiv(NN * HH * 32, 256), 256>>>(dfeat, al0, ar0, del, der);
        k_attn4<<<cdiv(NN * 32, 256), 256>>>(del, der, des, dra, nullptr);
        k_agg4<<<NN, 256>>>(dra, dfeat, nullptr, dout_l, 1);
    }

    // ---- GAT layer 1 ----
    {
        dim3 gg(cdiv(NN, GBM), cdiv(HDIM, GBN));
        gemm128<<<gg, 256>>>(dout_l, Wg1, dfeat, NN, HDIM, HDIM);
        k_es<<<NETT * HH, 64>>>(etab1, We1, ae1, des, HH);
        k_elr<<<cdiv(NN * HH * 32, 256), 256>>>(dfeat, al1, ar1, del, der);
        k_attn4<<<cdiv(NN * 32, 256), 256>>>(del, der, des, da, dra);
        k_agg4<<<NN, 256>>>(da, dfeat, dout_l, dout_l, 1);
    }

    // ---- GAT layer 2 (H=1, C=16) ----
    {
        k_copyB2<<<cdiv(32 * 256, 256), 256>>>(Wg2, resW2);
        dim3 gg(cdiv(NN, BM), 1);
        gemm_nt<<<gg, 256>>>(dout_l, dB2, nullptr, dfeat, NN, 32, HDIM);  // [N,32]: feat2|res2
        k_es<<<NETT * 1, 64>>>(etab2, We2, ae2, des, 1);
        k_elr2<<<cdiv(NN, 256), 256>>>(dfeat, al2, ar2, del, der);
        k_attn1<<<cdiv(NN * 32, 256), 256>>>(del, der, des, da);
        k_agg2<<<cdiv(NN * 16, 256), 256>>>(da, dfeat, out);
    }
}